// round 11
// baseline (speedup 1.0000x reference)
#include <cuda_runtime.h>
#include <cuda_bf16.h>
#include <cstdint>

// Problem constants (fixed by the dataset): N=100000, E=1600000, D=C=128.
#define NN 100000
#define EE 1600000
#define WTOT 212992  // total W elements across the 5 GEMMs

// Scratch (device globals — no allocations allowed anywhere).
__device__ __align__(16) float g_dinv[NN];
__device__ __align__(16) float g_xw[(size_t)NN * 256];
__device__ __align__(16) float g_g1[(size_t)NN * 256];
__device__ __align__(16) float g_g2[(size_t)NN * 128];
__device__ int g_rowcnt[NN];
__device__ int g_rowstart[NN + 1];
__device__ int g_rowfill[NN];
__device__ int g_csr_src[EE];
// Weights converted to bf16 hi/lo, transposed to K-major [N][K]:
__device__ __align__(16) __nv_bfloat16 g_Whi[WTOT];
__device__ __align__(16) __nv_bfloat16 g_Wlo[WTOT];

#define BUF_NONE 0
#define BUF_XW   1
#define BUF_G1   2
#define BUF_G2   3

__device__ __forceinline__ float* resolve(float* p, int id) {
    switch (id) {
        case BUF_XW: return g_xw;
        case BUF_G1: return g_g1;
        case BUF_G2: return g_g2;
        default: return p;
    }
}
__device__ __forceinline__ const float* resolve_c(const float* p, int id) {
    switch (id) {
        case BUF_XW: return g_xw;
        case BUF_G1: return g_g1;
        case BUF_G2: return g_g2;
        default: return p;
    }
}

// ---------------------------------------------------------------------------
// Warp-level tensor-core primitives (plain sm_103-safe PTX: ldmatrix + mma).
// ---------------------------------------------------------------------------
__device__ __forceinline__ uint32_t smem_u32(const void* p) {
    uint32_t a;
    asm("{ .reg .u64 t; cvta.to.shared.u64 t, %1; cvt.u32.u64 %0, t; }"
        : "=r"(a) : "l"(p));
    return a;
}
__device__ __forceinline__ void ldm_x4(uint32_t& r0, uint32_t& r1, uint32_t& r2,
                                       uint32_t& r3, uint32_t addr) {
    asm volatile("ldmatrix.sync.aligned.m8n8.x4.shared.b16 {%0,%1,%2,%3}, [%4];"
                 : "=r"(r0), "=r"(r1), "=r"(r2), "=r"(r3) : "r"(addr));
}
__device__ __forceinline__ void ldm_x2(uint32_t& r0, uint32_t& r1, uint32_t addr) {
    asm volatile("ldmatrix.sync.aligned.m8n8.x2.shared.b16 {%0,%1}, [%2];"
                 : "=r"(r0), "=r"(r1) : "r"(addr));
}
__device__ __forceinline__ void mma_bf16(float* c, const uint32_t* a,
                                         const uint32_t* b) {
    asm volatile(
        "mma.sync.aligned.m16n8k16.row.col.f32.bf16.bf16.f32 "
        "{%0,%1,%2,%3}, {%4,%5,%6,%7}, {%8,%9}, {%0,%1,%2,%3};"
        : "+f"(c[0]), "+f"(c[1]), "+f"(c[2]), "+f"(c[3])
        : "r"(a[0]), "r"(a[1]), "r"(a[2]), "r"(a[3]), "r"(b[0]), "r"(b[1]));
}

// ---------------------------------------------------------------------------
// CSR construction
// ---------------------------------------------------------------------------
__global__ void zero_cnt_kernel(int n) {
    int i = blockIdx.x * blockDim.x + threadIdx.x;
    if (i < n) g_rowcnt[i] = 0;
}
__global__ void count_dst_kernel(const int* __restrict__ dst, int E) {
    for (int e = blockIdx.x * blockDim.x + threadIdx.x; e < E;
         e += gridDim.x * blockDim.x)
        atomicAdd(g_rowcnt + dst[e], 1);
}
__global__ __launch_bounds__(1024) void scan_kernel(int n) {
    __shared__ int sums[1024];
    const int tid = threadIdx.x;
    const int chunk = (n + 1023) >> 10;
    const int begin = tid * chunk;
    const int end = min(begin + chunk, n);
    int s = 0;
    for (int i = begin; i < end; i++) s += g_rowcnt[i];
    sums[tid] = s;
    __syncthreads();
#pragma unroll
    for (int off = 1; off < 1024; off <<= 1) {
        int add = (tid >= off) ? sums[tid - off] : 0;
        __syncthreads();
        sums[tid] += add;
        __syncthreads();
    }
    if (tid == 0) g_rowstart[n] = sums[1023];
    int prefix = (tid > 0) ? sums[tid - 1] : 0;
    for (int i = begin; i < end; i++) {
        int c = g_rowcnt[i];
        g_rowstart[i] = prefix;
        g_rowfill[i] = prefix;
        g_dinv[i] = rsqrtf((float)(c + 1));
        prefix += c;
    }
}
__global__ void csr_fill_kernel(const int* __restrict__ src,
                                const int* __restrict__ dst, int E) {
    for (int e = blockIdx.x * blockDim.x + threadIdx.x; e < E;
         e += gridDim.x * blockDim.x) {
        int d = dst[e];
        int pos = atomicAdd(g_rowfill + d, 1);
        g_csr_src[pos] = src[e];
    }
}

// ---------------------------------------------------------------------------
// W preprocessing: W[K,Nout] fp32 -> K-major [Nout,K] bf16 hi/lo
// ---------------------------------------------------------------------------
__global__ void prep_w_kernel(const float* __restrict__ W, int K, int Nout, int woff) {
    int total = K * Nout;
    for (int idx = blockIdx.x * blockDim.x + threadIdx.x; idx < total;
         idx += gridDim.x * blockDim.x) {
        int n = idx / K, k = idx % K;
        float v = W[(size_t)k * Nout + n];
        __nv_bfloat16 h = __float2bfloat16(v);
        g_Whi[woff + idx] = h;
        g_Wlo[woff + idx] = __float2bfloat16(v - __bfloat162float(h));
    }
}

// ---------------------------------------------------------------------------
// Gather aggregation (one warp per destination node), self-loop+bias fused.
// ---------------------------------------------------------------------------
template <int F>
__global__ void gather_agg_kernel(const float* __restrict__ bias,
                                  float* outp, int out_id, int n) {
    float* __restrict__ out = resolve(outp, out_id);
    const int warp = (blockIdx.x * blockDim.x + threadIdx.x) >> 5;
    const int lane = threadIdx.x & 31;
    if (warp >= n) return;
    const int node = warp;
    const int f0 = lane * 4;
    constexpr int NH = F / 128;

    const float din = g_dinv[node];
    const float s2 = din * din;
    const float* xn = g_xw + (size_t)node * F;

    float4 acc[NH];
#pragma unroll
    for (int h = 0; h < NH; h++) {
        float4 v = *(const float4*)(xn + f0 + h * 128);
        float4 b = *(const float4*)(bias + f0 + h * 128);
        acc[h].x = fmaf(v.x, s2, b.x);
        acc[h].y = fmaf(v.y, s2, b.y);
        acc[h].z = fmaf(v.z, s2, b.z);
        acc[h].w = fmaf(v.w, s2, b.w);
    }
    const int rs = g_rowstart[node];
    const int re = g_rowstart[node + 1];
    for (int e = rs; e < re; e++) {
        int s = g_csr_src[e];
        float c = g_dinv[s] * din;
        const float* xp = g_xw + (size_t)s * F;
#pragma unroll
        for (int h = 0; h < NH; h++) {
            float4 v = *(const float4*)(xp + f0 + h * 128);
            acc[h].x = fmaf(v.x, c, acc[h].x);
            acc[h].y = fmaf(v.y, c, acc[h].y);
            acc[h].z = fmaf(v.z, c, acc[h].z);
            acc[h].w = fmaf(v.w, c, acc[h].w);
        }
    }
    float* op = out + (size_t)node * F;
#pragma unroll
    for (int h = 0; h < NH; h++) *(float4*)(op + f0 + h * 128) = acc[h];
}

// ---------------------------------------------------------------------------
// Tensor-core segmented GEMM via mma.sync, bf16 hi/lo compensated:
//   acc(fp32) += Ahi*Bhi + Alo*Bhi + Ahi*Blo     (residual ~2^-18)
// Block tile 128x128, BK=32, 8 warps (warp tile 64x32 = 4x4 m16n8k16 atoms).
// A converted fp32->bf16 hi/lo in-kernel; B read pre-split from g_Whi/g_Wlo.
// smem stride 40 b16 (80B) => ldmatrix row addresses conflict-free.
// ---------------------------------------------------------------------------
__device__ __forceinline__ float4 fetch_a4(const float* A0, int K0,
                                           const float* A1, int K1,
                                           const float* A2, int K2,
                                           int row, int k) {
    if (k < K0) return *(const float4*)(A0 + (size_t)row * K0 + k);
    k -= K0;
    if (k < K1) return *(const float4*)(A1 + (size_t)row * K1 + k);
    k -= K1;
    return *(const float4*)(A2 + (size_t)row * K2 + k);
}

__device__ __forceinline__ uint32_t pack_bf2(__nv_bfloat16 a, __nv_bfloat16 b) {
    return (uint32_t)__bfloat16_as_ushort(a) | ((uint32_t)__bfloat16_as_ushort(b) << 16);
}

template <bool RELU>
__global__ __launch_bounds__(256, 1) void gemm_mma_kernel(
    const float* A0p, int id0, int K0,
    const float* A1p, int id1, int K1,
    const float* A2p, int id2, int K2,
    int woff, const float* __restrict__ bias,
    float* Cp, int idC, int M, int Nout) {
    const float* __restrict__ A0 = resolve_c(A0p, id0);
    const float* __restrict__ A1 = resolve_c(A1p, id1);
    const float* __restrict__ A2 = resolve_c(A2p, id2);
    float* __restrict__ C = resolve(Cp, idC);
    const int Ktot = K0 + K1 + K2;

    __shared__ __align__(16) __nv_bfloat16 Ah[128][40];
    __shared__ __align__(16) __nv_bfloat16 Al[128][40];
    __shared__ __align__(16) __nv_bfloat16 Bh[128][40];
    __shared__ __align__(16) __nv_bfloat16 Bl[128][40];

    const int tid = threadIdx.x;
    const int wid = tid >> 5;
    const int lane = tid & 31;
    const int wm = wid >> 2;   // 0..1 -> 64-row slab
    const int wn = wid & 3;    // 0..3 -> 32-col slab
    const int bm = blockIdx.x * 128;
    const int bn = blockIdx.y * 128;

    const __nv_bfloat16* Wh = g_Whi + woff;
    const __nv_bfloat16* Wl = g_Wlo + woff;

    const uint32_t sAh = smem_u32(Ah), sAl = smem_u32(Al);
    const uint32_t sBh = smem_u32(Bh), sBl = smem_u32(Bl);

    // ldmatrix base offsets (bytes), before the ks*2 k-step offset.
    uint32_t aoff[4], boff[4];
    {
        int l16 = lane & 15;
#pragma unroll
        for (int mi = 0; mi < 4; mi++) {
            int r = wm * 64 + mi * 16 + l16;
            aoff[mi] = (uint32_t)(r * 40 + (lane >> 4) * 8) * 2;
        }
#pragma unroll
        for (int ni = 0; ni < 4; ni++) {
            int nrow = wn * 32 + ni * 8 + (l16 & 7);
            boff[ni] = (uint32_t)(nrow * 40 + (l16 >> 3) * 8) * 2;
        }
    }

    float acc[4][4][4] = {};

    for (int k0 = 0; k0 < Ktot; k0 += 32) {
        // --- A: 128x32 fp32 -> bf16 hi/lo (guarded) ---
#pragma unroll
        for (int i = 0; i < 4; i++) {
            int idx = i * 256 + tid;
            int r = idx >> 3;
            int c4 = (idx & 7) * 4;
            int row = bm + r;
            float4 v = (row < M) ? fetch_a4(A0, K0, A1, K1, A2, K2, row, k0 + c4)
                                 : make_float4(0.f, 0.f, 0.f, 0.f);
            __nv_bfloat16 h0 = __float2bfloat16(v.x), h1 = __float2bfloat16(v.y);
            __nv_bfloat16 h2 = __float2bfloat16(v.z), h3 = __float2bfloat16(v.w);
            *(uint2*)&Ah[r][c4] = make_uint2(pack_bf2(h0, h1), pack_bf2(h2, h3));
            *(uint2*)&Al[r][c4] = make_uint2(
                pack_bf2(__float2bfloat16(v.x - __bfloat162float(h0)),
                         __float2bfloat16(v.y - __bfloat162float(h1))),
                pack_bf2(__float2bfloat16(v.z - __bfloat162float(h2)),
                         __float2bfloat16(v.w - __bfloat162float(h3))));
        }
        // --- B: 128 n-rows x 32 k bf16 hi/lo, straight copy ---
#pragma unroll
        for (int j = 0; j < 2; j++) {
            int idx = j * 256 + tid;
            int r = idx >> 2;
            int q = (idx & 3) * 8;
            size_t go = (size_t)(bn + r) * Ktot + k0 + q;
            *(uint4*)&Bh[r][q] = *(const uint4*)(Wh + go);
            *(uint4*)&Bl[r][q] = *(const uint4*)(Wl + go);
        }
        __syncthreads();

#pragma unroll
        for (int ks = 0; ks < 32; ks += 16) {
            uint32_t ah[4][4], al[4][4], bh[4][2], bl[4][2];
#pragma unroll
            for (int mi = 0; mi < 4; mi++) {
                ldm_x4(ah[mi][0], ah[mi][1], ah[mi][2], ah[mi][3],
                       sAh + aoff[mi] + ks * 2);
                ldm_x4(al[mi][0], al[mi][1], al[mi][2], al[mi][3],
                       sAl + aoff[mi] + ks * 2);
            }
#pragma unroll
            for (int ni = 0; ni < 4; ni++) {
                ldm_x2(bh[ni][0], bh[ni][1], sBh + boff[ni] + ks * 2);
                ldm_x2(bl[ni][0], bl[ni][1], sBl + boff[ni] + ks * 2);
            }
#pragma unroll
            for (int mi = 0; mi < 4; mi++)
#pragma unroll
                for (int ni = 0; ni < 4; ni++) {
                    mma_bf16(acc[mi][ni], ah[mi], bh[ni]);
                    mma_bf16(acc[mi][ni], al[mi], bh[ni]);
                    mma_bf16(acc[mi][ni], ah[mi], bl[ni]);
                }
        }
        __syncthreads();
    }

    // Epilogue: fragment layout -> gmem with bias/relu.
    const int qrow = lane >> 2;          // 0..7
    const int qcol = (lane & 3) * 2;     // 0,2,4,6
#pragma unroll
    for (int mi = 0; mi < 4; mi++) {
        int r0 = bm + wm * 64 + mi * 16 + qrow;
        int r1 = r0 + 8;
#pragma unroll
        for (int ni = 0; ni < 4; ni++) {
            int col = bn + wn * 32 + ni * 8 + qcol;
            float2 b2 = bias ? *(const float2*)(bias + col)
                             : make_float2(0.f, 0.f);
            float2 o0 = make_float2(acc[mi][ni][0] + b2.x, acc[mi][ni][1] + b2.y);
            float2 o1 = make_float2(acc[mi][ni][2] + b2.x, acc[mi][ni][3] + b2.y);
            if (RELU) {
                o0.x = fmaxf(o0.x, 0.f); o0.y = fmaxf(o0.y, 0.f);
                o1.x = fmaxf(o1.x, 0.f); o1.y = fmaxf(o1.y, 0.f);
            }
            if (r0 < M) *(float2*)(C + (size_t)r0 * Nout + col) = o0;
            if (r1 < M) *(float2*)(C + (size_t)r1 * Nout + col) = o1;
        }
    }
}

// ---------------------------------------------------------------------------
// Launch
// ---------------------------------------------------------------------------
extern "C" void kernel_launch(void* const* d_in, const int* in_sizes, int n_in,
                              void* d_out, int out_size) {
    const float* x_self = (const float*)d_in[0];
    const float* x_nb   = (const float*)d_in[1];
    const int* ei = (const int*)d_in[2];  // int32 (JAX x64 disabled)
    const float* W_in_self  = (const float*)d_in[3];
    const float* b_in_self  = (const float*)d_in[4];
    const float* W_out_self = (const float*)d_in[5];
    const float* b_out_self = (const float*)d_in[6];
    const float* Wg1 = (const float*)d_in[7];
    const float* bg1 = (const float*)d_in[8];
    const float* Wg2 = (const float*)d_in[9];
    const float* bg2 = (const float*)d_in[10];
    const float* W_out = (const float*)d_in[11];
    const float* b_out = (const float*)d_in[12];

    const int N = in_sizes[0] / 128;
    const int E = in_sizes[2] / 2;
    const int* src = ei;
    const int* dst = ei + E;

    float* out_l1 = (float*)d_out;
    float* out_x2 = (float*)d_out + (size_t)N * 128;

    const int T = 256;
    const int gN = (N + T - 1) / T;
    const int gmx = (N + 127) / 128;
    const int gatherBlocks = (N + 7) / 8;

    // W offsets in g_Whi/g_Wlo ([N,K] K-major per GEMM)
    const int W1_OFF = 0;       // K=128,N=256
    const int W2_OFF = 32768;   // K=384,N=128
    const int W3_OFF = 81920;   // K=128,N=256
    const int W4_OFF = 114688;  // K=256,N=128
    const int W5_OFF = 147456;  // K=512,N=128

    // 0. weight conversion (tiny)
    prep_w_kernel<<<64, T>>>(W_in_self, 128, 256, W1_OFF);
    prep_w_kernel<<<64, T>>>(W_out_self, 384, 128, W2_OFF);
    prep_w_kernel<<<64, T>>>(Wg1, 128, 256, W3_OFF);
    prep_w_kernel<<<64, T>>>(Wg2, 256, 128, W4_OFF);
    prep_w_kernel<<<64, T>>>(W_out, 512, 128, W5_OFF);

    // 1. CSR build + degree normalization
    zero_cnt_kernel<<<gN, T>>>(N);
    count_dst_kernel<<<1024, T>>>(dst, E);
    scan_kernel<<<1, 1024>>>(N);
    csr_fill_kernel<<<1024, T>>>(src, dst, E);

    // 2. dense self branch
    gemm_mma_kernel<true><<<dim3(gmx, 2), T>>>(
        x_self, BUF_NONE, 128, nullptr, BUF_NONE, 0, nullptr, BUF_NONE, 0,
        W1_OFF, b_in_self, nullptr, BUF_XW, N, 256);
    gemm_mma_kernel<false><<<dim3(gmx, 1), T>>>(
        x_self, BUF_NONE, 128, nullptr, BUF_XW, 256, nullptr, BUF_NONE, 0,
        W2_OFF, b_out_self, out_l1, BUF_NONE, N, 128);

    // 3. gcn1
    gemm_mma_kernel<false><<<dim3(gmx, 2), T>>>(
        x_nb, BUF_NONE, 128, nullptr, BUF_NONE, 0, nullptr, BUF_NONE, 0,
        W3_OFF, nullptr, nullptr, BUF_XW, N, 256);
    gather_agg_kernel<256><<<gatherBlocks, T>>>(bg1, nullptr, BUF_G1, N);

    // 4. gcn2
    gemm_mma_kernel<false><<<dim3(gmx, 1), T>>>(
        nullptr, BUF_G1, 256, nullptr, BUF_NONE, 0, nullptr, BUF_NONE, 0,
        W4_OFF, nullptr, nullptr, BUF_XW, N, 128);
    gather_agg_kernel<128><<<gatherBlocks, T>>>(bg2, nullptr, BUF_G2, N);

    // 5. x2 = [x_nb | g1 | g2] @ W_out + b
    gemm_mma_kernel<false><<<dim3(gmx, 1), T>>>(
        x_nb, BUF_NONE, 128, nullptr, BUF_G1, 256, nullptr, BUF_G2, 128,
        W5_OFF, b_out, out_x2, BUF_NONE, N, 128);
}

// round 13
// speedup vs baseline: 1.4633x; 1.4633x over previous
#include <cuda_runtime.h>
#include <cuda_bf16.h>
#include <cstdint>

// Problem constants (fixed by the dataset): N=100000, E=1600000, D=C=128.
#define NN 100000
#define EE 1600000
#define WTOT 212992
// bf16 hi/lo activation pool: XS(128) XN(128) L1A(256) G1(256) G2(128) per node
#define HLTOT ((size_t)NN * 896)

// Scratch (device globals — no allocations allowed anywhere).
__device__ __align__(16) float g_dinv[NN];
__device__ __align__(16) float g_xw[(size_t)NN * 256];  // fp32 gather input
__device__ int g_rowcnt[NN];
__device__ int g_rowstart[NN + 1];
__device__ int g_rowfill[NN];
__device__ int g_csr_src[EE];
__device__ __align__(16) __nv_bfloat16 g_Whi[WTOT];   // weights K-major [N][K]
__device__ __align__(16) __nv_bfloat16 g_Wlo[WTOT];
__device__ __align__(16) __nv_bfloat16 g_Ahi[HLTOT];  // activations hi
__device__ __align__(16) __nv_bfloat16 g_Alo[HLTOT];  // activations lo

// Element offsets into g_Ahi/g_Alo (host-side constants, passed as args).
#define OFF_XS  0LL
#define OFF_XN  ((long long)NN * 128)
#define OFF_L1A ((long long)NN * 256)
#define OFF_G1  ((long long)NN * 512)
#define OFF_G2  ((long long)NN * 768)

// ---------------------------------------------------------------------------
// Primitives
// ---------------------------------------------------------------------------
__device__ __forceinline__ uint32_t smem_u32(const void* p) {
    uint32_t a;
    asm("{ .reg .u64 t; cvta.to.shared.u64 t, %1; cvt.u32.u64 %0, t; }"
        : "=r"(a) : "l"(p));
    return a;
}
__device__ __forceinline__ void ldm_x4(uint32_t& r0, uint32_t& r1, uint32_t& r2,
                                       uint32_t& r3, uint32_t addr) {
    asm volatile("ldmatrix.sync.aligned.m8n8.x4.shared.b16 {%0,%1,%2,%3}, [%4];"
                 : "=r"(r0), "=r"(r1), "=r"(r2), "=r"(r3) : "r"(addr));
}
__device__ __forceinline__ void ldm_x2(uint32_t& r0, uint32_t& r1, uint32_t addr) {
    asm volatile("ldmatrix.sync.aligned.m8n8.x2.shared.b16 {%0,%1}, [%2];"
                 : "=r"(r0), "=r"(r1) : "r"(addr));
}
__device__ __forceinline__ void mma_bf16(float* c, const uint32_t* a,
                                         const uint32_t* b) {
    asm volatile(
        "mma.sync.aligned.m16n8k16.row.col.f32.bf16.bf16.f32 "
        "{%0,%1,%2,%3}, {%4,%5,%6,%7}, {%8,%9}, {%0,%1,%2,%3};"
        : "+f"(c[0]), "+f"(c[1]), "+f"(c[2]), "+f"(c[3])
        : "r"(a[0]), "r"(a[1]), "r"(a[2]), "r"(a[3]), "r"(b[0]), "r"(b[1]));
}
__device__ __forceinline__ uint32_t pack_bf2(__nv_bfloat16 a, __nv_bfloat16 b) {
    return (uint32_t)__bfloat16_as_ushort(a) | ((uint32_t)__bfloat16_as_ushort(b) << 16);
}
__device__ __forceinline__ void split_bf(float v, __nv_bfloat16& h, __nv_bfloat16& l) {
    h = __float2bfloat16(v);
    l = __float2bfloat16(v - __bfloat162float(h));
}

// ---------------------------------------------------------------------------
// CSR construction
// ---------------------------------------------------------------------------
__global__ void zero_cnt_kernel(int n) {
    int i = blockIdx.x * blockDim.x + threadIdx.x;
    if (i < n) g_rowcnt[i] = 0;
}
__global__ void count_dst_kernel(const int* __restrict__ dst, int E) {
    for (int e = blockIdx.x * blockDim.x + threadIdx.x; e < E;
         e += gridDim.x * blockDim.x)
        atomicAdd(g_rowcnt + dst[e], 1);
}
__global__ __launch_bounds__(1024) void scan_kernel(int n) {
    __shared__ int sums[1024];
    const int tid = threadIdx.x;
    const int chunk = (n + 1023) >> 10;
    const int begin = tid * chunk;
    const int end = min(begin + chunk, n);
    int s = 0;
    for (int i = begin; i < end; i++) s += g_rowcnt[i];
    sums[tid] = s;
    __syncthreads();
#pragma unroll
    for (int off = 1; off < 1024; off <<= 1) {
        int add = (tid >= off) ? sums[tid - off] : 0;
        __syncthreads();
        sums[tid] += add;
        __syncthreads();
    }
    if (tid == 0) g_rowstart[n] = sums[1023];
    int prefix = (tid > 0) ? sums[tid - 1] : 0;
    for (int i = begin; i < end; i++) {
        int c = g_rowcnt[i];
        g_rowstart[i] = prefix;
        g_rowfill[i] = prefix;
        g_dinv[i] = rsqrtf((float)(c + 1));
        prefix += c;
    }
}
__global__ void csr_fill_kernel(const int* __restrict__ src,
                                const int* __restrict__ dst, int E) {
    for (int e = blockIdx.x * blockDim.x + threadIdx.x; e < E;
         e += gridDim.x * blockDim.x) {
        int d = dst[e];
        int pos = atomicAdd(g_rowfill + d, 1);
        g_csr_src[pos] = src[e];
    }
}

// ---------------------------------------------------------------------------
// Preprocessing: W[K,Nout] fp32 -> K-major [Nout][K] bf16 hi/lo;
//                activations fp32 -> hi/lo
// ---------------------------------------------------------------------------
__global__ void prep_w_kernel(const float* __restrict__ W, int K, int Nout, int woff) {
    int total = K * Nout;
    for (int idx = blockIdx.x * blockDim.x + threadIdx.x; idx < total;
         idx += gridDim.x * blockDim.x) {
        int n = idx / K, k = idx % K;
        float v = W[(size_t)k * Nout + n];
        __nv_bfloat16 h, l;
        split_bf(v, h, l);
        g_Whi[woff + idx] = h;
        g_Wlo[woff + idx] = l;
    }
}
__global__ void conv_hilo_kernel(const float* __restrict__ x, long long off,
                                 long long n4) {
    for (long long i = blockIdx.x * (long long)blockDim.x + threadIdx.x; i < n4;
         i += (long long)gridDim.x * blockDim.x) {
        float4 v = ((const float4*)x)[i];
        __nv_bfloat16 h0, l0, h1, l1, h2, l2, h3, l3;
        split_bf(v.x, h0, l0);
        split_bf(v.y, h1, l1);
        split_bf(v.z, h2, l2);
        split_bf(v.w, h3, l3);
        ((uint2*)(g_Ahi + off))[i] = make_uint2(pack_bf2(h0, h1), pack_bf2(h2, h3));
        ((uint2*)(g_Alo + off))[i] = make_uint2(pack_bf2(l0, l1), pack_bf2(l2, l3));
    }
}

// ---------------------------------------------------------------------------
// Gather aggregation (warp/node), fp32 internal, writes bf16 hi/lo:
//   out[d,:] = bias + xw[d,:]*dinv[d]^2 + sum_e xw[src,:]*dinv[src]*dinv[d]
// ---------------------------------------------------------------------------
template <int F>
__global__ void gather_agg_kernel(const float* __restrict__ bias,
                                  long long out_off, int n) {
    const int warp = (blockIdx.x * blockDim.x + threadIdx.x) >> 5;
    const int lane = threadIdx.x & 31;
    if (warp >= n) return;
    const int node = warp;
    const int f0 = lane * 4;
    constexpr int NH = F / 128;

    const float din = g_dinv[node];
    const float s2 = din * din;
    const float* xn = g_xw + (size_t)node * F;

    float4 acc[NH];
#pragma unroll
    for (int h = 0; h < NH; h++) {
        float4 v = *(const float4*)(xn + f0 + h * 128);
        float4 b = *(const float4*)(bias + f0 + h * 128);
        acc[h].x = fmaf(v.x, s2, b.x);
        acc[h].y = fmaf(v.y, s2, b.y);
        acc[h].z = fmaf(v.z, s2, b.z);
        acc[h].w = fmaf(v.w, s2, b.w);
    }
    const int rs = g_rowstart[node];
    const int re = g_rowstart[node + 1];
    for (int e = rs; e < re; e++) {
        int s = g_csr_src[e];
        float c = g_dinv[s] * din;
        const float* xp = g_xw + (size_t)s * F;
#pragma unroll
        for (int h = 0; h < NH; h++) {
            float4 v = *(const float4*)(xp + f0 + h * 128);
            acc[h].x = fmaf(v.x, c, acc[h].x);
            acc[h].y = fmaf(v.y, c, acc[h].y);
            acc[h].z = fmaf(v.z, c, acc[h].z);
            acc[h].w = fmaf(v.w, c, acc[h].w);
        }
    }
    size_t base = (size_t)out_off + (size_t)node * F + f0;
#pragma unroll
    for (int h = 0; h < NH; h++) {
        __nv_bfloat16 h0, l0, h1, l1, h2, l2, h3, l3;
        split_bf(acc[h].x, h0, l0);
        split_bf(acc[h].y, h1, l1);
        split_bf(acc[h].z, h2, l2);
        split_bf(acc[h].w, h3, l3);
        *(uint2*)(g_Ahi + base + h * 128) =
            make_uint2(pack_bf2(h0, h1), pack_bf2(h2, h3));
        *(uint2*)(g_Alo + base + h * 128) =
            make_uint2(pack_bf2(l0, l1), pack_bf2(l2, l3));
    }
}

// ---------------------------------------------------------------------------
// Tensor-core segmented GEMM (mma.sync bf16 hi/lo compensated):
//   acc(fp32) += Ahi*Bhi + Alo*Bhi + Ahi*Blo    (residual ~2^-18)
// Block 128x128, BK=32, 8 warps, warp tile 64x32. A/B pre-split bf16 hi/lo in
// gmem -> loader is pure uint4 copies, register-prefetched one chunk ahead.
// smem stride 40 b16 -> ldmatrix conflict-free.
// ---------------------------------------------------------------------------
__device__ __forceinline__ size_t seg_off(long long o0, int k0w, long long o1,
                                          int k1w, long long o2, int k2w,
                                          int row, int k) {
    if (k < k0w) return (size_t)o0 + (size_t)row * k0w + k;
    k -= k0w;
    if (k < k1w) return (size_t)o1 + (size_t)row * k1w + k;
    k -= k1w;
    return (size_t)o2 + (size_t)row * k2w + k;
}

template <bool RELU, bool OUT_HILO>
__global__ __launch_bounds__(256) void gemm_mma_kernel(
    long long o0, int k0w, long long o1, int k1w, long long o2, int k2w,
    int woff, const float* __restrict__ bias,
    float* Cf, int idC, long long c_off, int M, int Nout) {
    float* __restrict__ C = (idC == 1) ? g_xw : Cf;
    const int Ktot = k0w + k1w + k2w;

    __shared__ __align__(16) __nv_bfloat16 Ah[128][40];
    __shared__ __align__(16) __nv_bfloat16 Al[128][40];
    __shared__ __align__(16) __nv_bfloat16 Bh[128][40];
    __shared__ __align__(16) __nv_bfloat16 Bl[128][40];

    const int tid = threadIdx.x;
    const int wid = tid >> 5;
    const int lane = tid & 31;
    const int wm = wid >> 2;
    const int wn = wid & 3;
    const int bm = blockIdx.x * 128;
    const int bn = blockIdx.y * 128;

    const __nv_bfloat16* Wh = g_Whi + woff;
    const __nv_bfloat16* Wl = g_Wlo + woff;

    // Loader coordinates (fixed per thread): 512 uint4 tasks per operand.
    int ra[2], qa[2], rb[2], qb[2];
#pragma unroll
    for (int i = 0; i < 2; i++) {
        int t = i * 256 + tid;
        ra[i] = t >> 2;
        qa[i] = (t & 3) * 8;
        rb[i] = ra[i];
        qb[i] = qa[i];
    }

    const uint32_t sAh = smem_u32(Ah), sAl = smem_u32(Al);
    const uint32_t sBh = smem_u32(Bh), sBl = smem_u32(Bl);

    uint32_t aoff[4], boff[4];
    {
        int l16 = lane & 15;
#pragma unroll
        for (int mi = 0; mi < 4; mi++) {
            int r = wm * 64 + mi * 16 + l16;
            aoff[mi] = (uint32_t)(r * 40 + (lane >> 4) * 8) * 2;
        }
#pragma unroll
        for (int ni = 0; ni < 4; ni++) {
            int nrow = wn * 32 + ni * 8 + (l16 & 7);
            boff[ni] = (uint32_t)(nrow * 40 + (l16 >> 3) * 8) * 2;
        }
    }

    uint4 pAh[2], pAl[2], pBh[2], pBl[2];
    const uint4 z4 = make_uint4(0, 0, 0, 0);

    auto load_chunk = [&](int k0) {
#pragma unroll
        for (int i = 0; i < 2; i++) {
            int row = bm + ra[i];
            if (row < M) {
                size_t off = seg_off(o0, k0w, o1, k1w, o2, k2w, row, k0 + qa[i]);
                pAh[i] = *(const uint4*)(g_Ahi + off);
                pAl[i] = *(const uint4*)(g_Alo + off);
            } else {
                pAh[i] = z4;
                pAl[i] = z4;
            }
            size_t go = (size_t)(bn + rb[i]) * Ktot + k0 + qb[i];
            pBh[i] = *(const uint4*)(Wh + go);
            pBl[i] = *(const uint4*)(Wl + go);
        }
    };
    auto store_chunk = [&]() {
#pragma unroll
        for (int i = 0; i < 2; i++) {
            *(uint4*)&Ah[ra[i]][qa[i]] = pAh[i];
            *(uint4*)&Al[ra[i]][qa[i]] = pAl[i];
            *(uint4*)&Bh[rb[i]][qb[i]] = pBh[i];
            *(uint4*)&Bl[rb[i]][qb[i]] = pBl[i];
        }
    };

    float acc[4][4][4] = {};
    const int nch = Ktot >> 5;

    load_chunk(0);
    store_chunk();
    __syncthreads();

    for (int ch = 0; ch < nch; ch++) {
        const bool more = (ch + 1) < nch;
        if (more) load_chunk((ch + 1) << 5);  // gmem loads overlap the MMAs

#pragma unroll
        for (int ks = 0; ks < 32; ks += 16) {
            uint32_t ah[4][4], al[4][4], bh[4][2], bl[4][2];
#pragma unroll
            for (int mi = 0; mi < 4; mi++) {
                ldm_x4(ah[mi][0], ah[mi][1], ah[mi][2], ah[mi][3],
                       sAh + aoff[mi] + ks * 2);
                ldm_x4(al[mi][0], al[mi][1], al[mi][2], al[mi][3],
                       sAl + aoff[mi] + ks * 2);
            }
#pragma unroll
            for (int ni = 0; ni < 4; ni++) {
                ldm_x2(bh[ni][0], bh[ni][1], sBh + boff[ni] + ks * 2);
                ldm_x2(bl[ni][0], bl[ni][1], sBl + boff[ni] + ks * 2);
            }
#pragma unroll
            for (int mi = 0; mi < 4; mi++)
#pragma unroll
                for (int ni = 0; ni < 4; ni++) {
                    mma_bf16(acc[mi][ni], ah[mi], bh[ni]);
                    mma_bf16(acc[mi][ni], al[mi], bh[ni]);
                    mma_bf16(acc[mi][ni], ah[mi], bl[ni]);
                }
        }
        __syncthreads();
        if (more) {
            store_chunk();
            __syncthreads();
        }
    }

    // Epilogue
    const int qrow = lane >> 2;
    const int qcol = (lane & 3) * 2;
#pragma unroll
    for (int mi = 0; mi < 4; mi++) {
        int r0 = bm + wm * 64 + mi * 16 + qrow;
        int r1 = r0 + 8;
#pragma unroll
        for (int ni = 0; ni < 4; ni++) {
            int col = bn + wn * 32 + ni * 8 + qcol;
            float2 b2 = bias ? *(const float2*)(bias + col) : make_float2(0.f, 0.f);
            float2 o0 = make_float2(acc[mi][ni][0] + b2.x, acc[mi][ni][1] + b2.y);
            float2 o1 = make_float2(acc[mi][ni][2] + b2.x, acc[mi][ni][3] + b2.y);
            if (RELU) {
                o0.x = fmaxf(o0.x, 0.f); o0.y = fmaxf(o0.y, 0.f);
                o1.x = fmaxf(o1.x, 0.f); o1.y = fmaxf(o1.y, 0.f);
            }
            if (OUT_HILO) {
                if (r0 < M) {
                    __nv_bfloat16 h0, l0, h1, l1;
                    split_bf(o0.x, h0, l0);
                    split_bf(o0.y, h1, l1);
                    size_t p = (size_t)c_off + (size_t)r0 * Nout + col;
                    *(uint32_t*)(g_Ahi + p) = pack_bf2(h0, h1);
                    *(uint32_t*)(g_Alo + p) = pack_bf2(l0, l1);
                }
                if (r1 < M) {
                    __nv_bfloat16 h0, l0, h1, l1;
                    split_bf(o1.x, h0, l0);
                    split_bf(o1.y, h1, l1);
                    size_t p = (size_t)c_off + (size_t)r1 * Nout + col;
                    *(uint32_t*)(g_Ahi + p) = pack_bf2(h0, h1);
                    *(uint32_t*)(g_Alo + p) = pack_bf2(l0, l1);
                }
            } else {
                if (r0 < M) *(float2*)(C + (size_t)r0 * Nout + col) = o0;
                if (r1 < M) *(float2*)(C + (size_t)r1 * Nout + col) = o1;
            }
        }
    }
}

// ---------------------------------------------------------------------------
// Launch
// ---------------------------------------------------------------------------
extern "C" void kernel_launch(void* const* d_in, const int* in_sizes, int n_in,
                              void* d_out, int out_size) {
    const float* x_self = (const float*)d_in[0];
    const float* x_nb   = (const float*)d_in[1];
    const int* ei = (const int*)d_in[2];  // int32 (JAX x64 disabled)
    const float* W_in_self  = (const float*)d_in[3];
    const float* b_in_self  = (const float*)d_in[4];
    const float* W_out_self = (const float*)d_in[5];
    const float* b_out_self = (const float*)d_in[6];
    const float* Wg1 = (const float*)d_in[7];
    const float* bg1 = (const float*)d_in[8];
    const float* Wg2 = (const float*)d_in[9];
    const float* bg2 = (const float*)d_in[10];
    const float* W_out = (const float*)d_in[11];
    const float* b_out = (const float*)d_in[12];

    const int N = in_sizes[0] / 128;
    const int E = in_sizes[2] / 2;
    const int* src = ei;
    const int* dst = ei + E;

    float* out_l1 = (float*)d_out;
    float* out_x2 = (float*)d_out + (size_t)N * 128;

    const int T = 256;
    const int gN = (N + T - 1) / T;
    const int gmx = (N + 127) / 128;
    const int gatherBlocks = (N + 7) / 8;

    // W offsets ([N][K] K-major per GEMM)
    const int W1_OFF = 0;       // K=128,N=256
    const int W2_OFF = 32768;   // K=384,N=128
    const int W3_OFF = 81920;   // K=128,N=256
    const int W4_OFF = 114688;  // K=256,N=128
    const int W5_OFF = 147456;  // K=512,N=128

    // 0. conversions (weights + input activations)
    prep_w_kernel<<<64, T>>>(W_in_self, 128, 256, W1_OFF);
    prep_w_kernel<<<64, T>>>(W_out_self, 384, 128, W2_OFF);
    prep_w_kernel<<<64, T>>>(Wg1, 128, 256, W3_OFF);
    prep_w_kernel<<<64, T>>>(Wg2, 256, 128, W4_OFF);
    prep_w_kernel<<<64, T>>>(W_out, 512, 128, W5_OFF);
    conv_hilo_kernel<<<512, T>>>(x_self, OFF_XS, (long long)N * 32);
    conv_hilo_kernel<<<512, T>>>(x_nb, OFF_XN, (long long)N * 32);

    // 1. CSR build + degree normalization
    zero_cnt_kernel<<<gN, T>>>(N);
    count_dst_kernel<<<1024, T>>>(dst, E);
    scan_kernel<<<1, 1024>>>(N);
    csr_fill_kernel<<<1024, T>>>(src, dst, E);

    // 2. dense self branch: l1a = relu(x_self@W1 + b) -> hi/lo L1A
    gemm_mma_kernel<true, true><<<dim3(gmx, 2), T>>>(
        OFF_XS, 128, 0, 0, 0, 0, W1_OFF, b_in_self, nullptr, 0, OFF_L1A, N, 256);
    //    l1 = [x_self | l1a] @ W2 + b -> out_l1 (fp32 output)
    gemm_mma_kernel<false, false><<<dim3(gmx, 1), T>>>(
        OFF_XS, 128, OFF_L1A, 256, 0, 0, W2_OFF, b_out_self, out_l1, 0, 0, N, 128);

    // 3. gcn1: xw = x_nb @ Wg1 (fp32) ; g1 = bias+selfloop+gather -> hi/lo G1
    gemm_mma_kernel<false, false><<<dim3(gmx, 2), T>>>(
        OFF_XN, 128, 0, 0, 0, 0, W3_OFF, nullptr, nullptr, 1, 0, N, 256);
    gather_agg_kernel<256><<<gatherBlocks, T>>>(bg1, OFF_G1, N);

    // 4. gcn2: xw = g1 @ Wg2 (fp32) ; g2 -> hi/lo G2
    gemm_mma_kernel<false, false><<<dim3(gmx, 1), T>>>(
        OFF_G1, 256, 0, 0, 0, 0, W4_OFF, nullptr, nullptr, 1, 0, N, 128);
    gather_agg_kernel<128><<<gatherBlocks, T>>>(bg2, OFF_G2, N);

    // 5. x2 = [x_nb | g1 | g2] @ W_out + b -> out_x2 (fp32 output)
    gemm_mma_kernel<false, false><<<dim3(gmx, 1), T>>>(
        OFF_XN, 128, OFF_G1, 256, OFF_G2, 128, W5_OFF, b_out, out_x2, 0, 0, N, 128);
}